// round 16
// baseline (speedup 1.0000x reference)
#include <cuda_runtime.h>
#include <math.h>

#define HH 2048
#define WW 2048
#define NIMG 4
#define TOT (NIMG*HH*WW)
#define RANK0 8388607u   // (TOT-1)/2

// harris tile geometry (32x32 output tile)
#define TR 32
#define TC 32
#define GR 40            // TR+8
#define SXR 42           // TR+10
#define SXW 48           // x tile cols (rel -8..39), float4-friendly
#define PX  52           // x pitch (multiple of 4 for STS.128)
#define PIX 41           // Ixy pitch (float2 units, odd)
#define PSH 33           // smoothed pitch (odd; float2 units for sS01, floats for sS2)
#define SIXY2 (GR*PIX)             // 1640 float2 = 3280 floats
#define SHCH2 (GR*PSH)             // 1320 float2 (sS01) / 1320 floats (sS2)
#define SC_FLOATS (3*SHCH2)        // 3960 floats total (2640 for sS01 + 1320 for sS2)
#define SMEM_FLOATS (2*SIXY2 + SC_FLOATS)  // 7240
#define SMEM_BYTES (SMEM_FLOATS*4)         // 28960
#define HARRIS_BLOCKS ((WW/TC)*(HH/TR)*NIMG)  // 16384

// ---------------- device scratch ----------------
__device__ float    g_R[TOT];
__device__ unsigned g_hist[2048];
__device__ unsigned g_prefix, g_rank;
__device__ unsigned g_done1, g_done2, g_done3, g_phase;
__device__ float    g_med;

// ---------------- shared select: warp-shuffle scan (2 barriers) ----------------
__device__ __forceinline__ void select_pass(int shift, int nbits) {
    __shared__ unsigned swsum[8];
    __shared__ unsigned sbase[8];
    const int nb = 1 << nbits;
    const int per = nb >> 8;
    const int t = threadIdx.x;
    const int lane = t & 31;
    const int wid  = t >> 5;
    unsigned pfx, rank;
    if (shift == 21) { pfx = 0u; rank = RANK0; }
    else {
        pfx  = *(volatile unsigned*)&g_prefix;
        rank = *(volatile unsigned*)&g_rank;
    }

    unsigned local[8];
    unsigned sum = 0;
    for (int i = 0; i < per; i++) {
        local[i] = *(volatile unsigned*)&g_hist[t*per + i];
        sum += local[i];
    }
    unsigned run = sum;
    #pragma unroll
    for (int d = 1; d < 32; d <<= 1) {
        unsigned v = __shfl_up_sync(0xFFFFFFFFu, run, d);
        if (lane >= d) run += v;
    }
    if (lane == 31) swsum[wid] = run;
    __syncthreads();
    if (t < 8) {
        unsigned v = swsum[t];
        unsigned r = v;
        #pragma unroll
        for (int d = 1; d < 8; d <<= 1) {
            unsigned u = __shfl_up_sync(0xFFu, r, d, 8);
            if (t >= d) r += u;
        }
        sbase[t] = r - v;
    }
    __syncthreads();
    unsigned before = sbase[wid] + (run - sum);
    if (rank >= before && rank < before + sum) {
        unsigned cum = before;
        for (int i = 0; i < per; i++) {
            if (rank < cum + local[i]) {
                unsigned bin = (unsigned)(t*per + i);
                unsigned np = pfx | (bin << shift);
                g_prefix = np;
                g_rank = rank - cum;
                if (shift == 0) {
                    unsigned bb = (np & 0x80000000u) ? (np ^ 0x80000000u) : ~np;
                    g_med = __uint_as_float(bb);
                }
                break;
            }
            cum += local[i];
        }
    }
    __syncthreads();
    for (int i = t; i < nb; i += 256) g_hist[i] = 0;
}

// ---------------- fused Sobel + products + separable gauss + R + hist1 ----------------
__global__ __launch_bounds__(256) void k_harris(const float* __restrict__ x,
                                                const float* __restrict__ g2) {
    extern __shared__ float smem[];
    float2* sIxy = (float2*)smem;          // GR x PIX float2 (Ix,Iy)
    float*  sC   = smem + 2*SIXY2;         // union: x tile (SXR*PX) then sS01/sS2
    float2* sS01 = (float2*)sC;            // GR x PSH float2 (Sxx,Syy)
    float*  sS2  = sC + 2*SHCH2;           // GR x PSH floats (Sxy)
    unsigned* shist = (unsigned*)smem;     // aliases sIxy in phase 4

    __shared__ float s_w[9];
    __shared__ unsigned s_last;

    const int t = threadIdx.x;
    const int lane = t & 31;
    const int wid  = t >> 5;
    const int n   = blockIdx.z;
    const int r0g = blockIdx.y * TR;
    const int c0g = blockIdx.x * TC;
    const float* __restrict__ xi = x + (size_t)n * HH * WW;

    if (t == 0) {
        double c = sqrt((double)g2[4*9 + 4]);
        for (int k = 0; k < 9; k++) s_w[k] = (float)((double)g2[4*9 + k] / c);
    }

    const bool interior = (blockIdx.x > 0) && (blockIdx.x < WW/TC - 1) &&
                          (blockIdx.y > 0) && (blockIdx.y < HH/TR - 1);

    // ---- phase 1: load x tile rows -5..36, cols -8..39 (float4 interior) ----
    if (interior) {
        const float* base = xi + (size_t)(r0g - 5) * WW + (c0g - 8);   // 16B aligned
        for (int idx = t; idx < SXR*12; idx += 256) {
            int i = idx / 12, j4 = idx % 12;
            float4 v = *(const float4*)(base + (size_t)i * WW + j4*4);
            *(float4*)&sC[i*PX + j4*4] = v;
        }
    } else {
        for (int idx = t; idx < SXR*SXW; idx += 256) {
            int i = idx / SXW, j = idx % SXW;
            int gr = r0g + i - 5, gc = c0g + j - 8;
            float v = 0.f;
            if (gr >= 0 && gr < HH && gc >= 0 && gc < WW) v = xi[(size_t)gr * WW + gc];
            sC[i*PX + j] = v;
        }
    }
    __syncthreads();

    float w[9];
    #pragma unroll
    for (int k = 0; k < 9; k++) w[k] = s_w[k];

    // ---- phase 2: sobel Ix,Iy at rel rows -4..35, rel cols -4..35 (packed stores) ----
    for (int task = t; task < GR*10; task += 256) {
        int i  = task / 10;
        int j0 = (task % 10) * 4;
        float a[3][6];
        #pragma unroll
        for (int r = 0; r < 3; r++)
            #pragma unroll
            for (int c = 0; c < 6; c++)
                a[r][c] = sC[(i + r)*PX + j0 + 3 + c];
        if (interior) {
            #pragma unroll
            for (int dj = 0; dj < 4; dj++) {
                float ix = (a[0][dj+2]-a[0][dj]) + 2.f*(a[1][dj+2]-a[1][dj]) + (a[2][dj+2]-a[2][dj]);
                float iy = (a[2][dj]-a[0][dj])   + 2.f*(a[2][dj+1]-a[0][dj+1]) + (a[2][dj+2]-a[0][dj+2]);
                sIxy[i*PIX + j0 + dj] = make_float2(ix, iy);
            }
        } else {
            int gr = r0g + i - 4;
            bool rok = (gr >= 0 && gr < HH);
            #pragma unroll
            for (int dj = 0; dj < 4; dj++) {
                int gc = c0g + j0 + dj - 4;
                float ix = 0.f, iy = 0.f;
                if (rok && gc >= 0 && gc < WW) {
                    ix = (a[0][dj+2]-a[0][dj]) + 2.f*(a[1][dj+2]-a[1][dj]) + (a[2][dj+2]-a[2][dj]);
                    iy = (a[2][dj]-a[0][dj])   + 2.f*(a[2][dj+1]-a[0][dj+1]) + (a[2][dj+2]-a[0][dj+2]);
                }
                sIxy[i*PIX + j0 + dj] = make_float2(ix, iy);
            }
        }
    }
    __syncthreads();

    // ---- phase 3: horizontal gauss of products; store packed (Sxx,Syy) + scalar Sxy ----
    for (int task = t; task < GR*8; task += 256) {
        int row = task >> 3;
        int j0  = (task & 7) << 2;
        const float2* bxy = &sIxy[row*PIX + j0];
        float ix[12], iy[12];
        #pragma unroll
        for (int p = 0; p < 12; p++) { float2 v = bxy[p]; ix[p] = v.x; iy[p] = v.y; }
        float s0[4] = {0,0,0,0}, s1[4] = {0,0,0,0}, s2[4] = {0,0,0,0};
        #pragma unroll
        for (int p = 0; p < 12; p++) {
            float pxx = ix[p]*ix[p];
            float pyy = iy[p]*iy[p];
            float pxy = ix[p]*iy[p];
            #pragma unroll
            for (int j = 0; j < 4; j++) {
                if (p - j >= 0 && p - j <= 8) {
                    float wk = w[p - j];
                    s0[j] += wk*pxx;
                    s1[j] += wk*pyy;
                    s2[j] += wk*pxy;
                }
            }
        }
        #pragma unroll
        for (int j = 0; j < 4; j++) {
            sS01[row*PSH + j0 + j] = make_float2(s0[j], s1[j]);
            sS2 [row*PSH + j0 + j] = s2[j];
        }
    }
    __syncthreads();

    for (int i = t; i < 2048; i += 256) shist[i] = 0;
    __syncthreads();

    // ---- phase 4: vertical gauss + R + histogram (4 rows/thread; packed loads) ----
    {
        const int col = lane;
        const int r0l = wid * 4;
        float w0[12], w1[12], win2[12];
        float s0[4], s1[4];

        #pragma unroll
        for (int k = 0; k < 12; k++) {
            float2 v = sS01[(r0l + k)*PSH + col];
            w0[k] = v.x; w1[k] = v.y;
        }
        #pragma unroll
        for (int o = 0; o < 4; o++) {
            float a = 0.f, b = 0.f;
            #pragma unroll
            for (int k = 0; k < 9; k++) {
                a += w[k]*w0[o + k];
                b += w[k]*w1[o + k];
            }
            s0[o] = a; s1[o] = b;
        }
        #pragma unroll
        for (int k = 0; k < 12; k++) win2[k] = sS2[(r0l + k)*PSH + col];

        size_t obase = (size_t)n * HH * WW + (size_t)(r0g + r0l) * WW + (c0g + col);
        #pragma unroll
        for (int o = 0; o < 4; o++) {
            float s2 = 0.f;
            #pragma unroll
            for (int k = 0; k < 9; k++) s2 += w[k]*win2[o + k];
            float det = s0[o]*s1[o] - s2*s2;
            float tr  = s0[o] + s1[o];
            float R   = det - 0.05f*tr*tr;
            g_R[obase + (size_t)o * WW] = R;

            unsigned b = __float_as_uint(R);
            unsigned u = b ^ ((b & 0x80000000u) ? 0xFFFFFFFFu : 0x80000000u);
            unsigned bin = u >> 21;
            unsigned peers = __match_any_sync(0xFFFFFFFFu, bin);
            if ((unsigned)(__ffs(peers) - 1) == (unsigned)lane)
                atomicAdd(&shist[bin], (unsigned)__popc(peers));
        }
    }
    __syncthreads();

    for (int i = t; i < 2048; i += 256) {
        unsigned c = shist[i];
        if (c) atomicAdd(&g_hist[i], c);
    }
    __threadfence();
    if (t == 0) s_last = (atomicAdd(&g_done1, 1) == HARRIS_BLOCKS - 1) ? 1u : 0u;
    __syncthreads();
    if (s_last) {
        __threadfence();
        select_pass(21, 11);
        if (t == 0) g_done1 = 0;
    }
}

// ---------------- fused passes 2+3: persistent kernel, 2x-unrolled scans ----------------
__global__ __launch_bounds__(256) void k_sel23() {
    __shared__ unsigned s_hist[2048];
    __shared__ unsigned s_last;
    const int t = threadIdx.x;
    const unsigned lane = t & 31;
    const float4* __restrict__ Rv = (const float4*)g_R;
    const size_t n4 = TOT / 4;
    const size_t stride = (size_t)gridDim.x * 256;

    for (int i = t; i < 2048; i += 256) s_hist[i] = 0;
    __syncthreads();

    const unsigned pfx_hi = g_prefix >> 21;
    for (size_t i4 = (size_t)blockIdx.x * 256 + t; i4 < n4; i4 += 2*stride) {
        float4 va = Rv[i4];
        float4 vb = Rv[i4 + stride];
        float vals[8] = {va.x, va.y, va.z, va.w, vb.x, vb.y, vb.z, vb.w};
        #pragma unroll
        for (int e = 0; e < 8; e++) {
            unsigned b = __float_as_uint(vals[e]);
            unsigned u = b ^ ((b & 0x80000000u) ? 0xFFFFFFFFu : 0x80000000u);
            bool match = ((u >> 21) == pfx_hi);
            unsigned bin = (u >> 10) & 2047u;
            unsigned bal = __ballot_sync(0xFFFFFFFFu, match);
            if (match) {
                unsigned peers = __match_any_sync(bal, bin);
                if ((unsigned)(__ffs(peers) - 1) == lane)
                    atomicAdd(&s_hist[bin], (unsigned)__popc(peers));
            }
        }
    }
    __syncthreads();
    for (int i = t; i < 2048; i += 256) {
        unsigned c = s_hist[i];
        if (c) atomicAdd(&g_hist[i], c);
    }
    __threadfence();
    if (t == 0) s_last = (atomicAdd(&g_done2, 1) == gridDim.x - 1) ? 1u : 0u;
    __syncthreads();
    if (s_last) {
        __threadfence();
        select_pass(10, 11);
        __threadfence();
        if (t == 0) atomicExch(&g_phase, 1u);
    } else {
        if (t == 0) { while (*(volatile unsigned*)&g_phase == 0u) __nanosleep(64); }
        __syncthreads();
    }

    for (int i = t; i < 1024; i += 256) s_hist[i] = 0;
    __syncthreads();

    const unsigned pfx = (*(volatile unsigned*)&g_prefix) >> 10;
    for (size_t i4 = (size_t)blockIdx.x * 256 + t; i4 < n4; i4 += 2*stride) {
        float4 va = Rv[i4];
        float4 vb = Rv[i4 + stride];
        float vals[8] = {va.x, va.y, va.z, va.w, vb.x, vb.y, vb.z, vb.w};
        #pragma unroll
        for (int e = 0; e < 8; e++) {
            unsigned b = __float_as_uint(vals[e]);
            unsigned u = b ^ ((b & 0x80000000u) ? 0xFFFFFFFFu : 0x80000000u);
            bool match = ((u >> 10) == pfx);
            unsigned bin = u & 1023u;
            unsigned bal = __ballot_sync(0xFFFFFFFFu, match);
            if (match) {
                unsigned peers = __match_any_sync(bal, bin);
                if ((unsigned)(__ffs(peers) - 1) == lane)
                    atomicAdd(&s_hist[bin], (unsigned)__popc(peers));
            }
        }
    }
    __syncthreads();
    for (int i = t; i < 1024; i += 256) {
        unsigned c = s_hist[i];
        if (c) atomicAdd(&g_hist[i], c);
    }
    __threadfence();
    if (t == 0) s_last = (atomicAdd(&g_done3, 1) == gridDim.x - 1) ? 1u : 0u;
    __syncthreads();
    if (s_last) {
        __threadfence();
        select_pass(0, 10);
        if (t == 0) { g_done2 = 0; g_done3 = 0; g_phase = 0; }
    }
}

// ---------------- threshold + 7x7 NMS (float4 loads, prefix/suffix max both axes) ----------------
#define PTX 44   // sxt pitch (multiple of 4 for STS.128)
#define PTM 33   // hmax pitch (odd)
__global__ __launch_bounds__(256) void k_pool(float* __restrict__ out) {
    __shared__ float sxt[70*PTX];
    __shared__ float shm[70*PTM];
    const int bx = blockIdx.x, by = blockIdx.y, n = blockIdx.z;
    const int r0 = by * 64, c0 = bx * 32;
    const float* __restrict__ Ri = g_R + (size_t)n * HH * WW;
    const float med = g_med;
    const float NEG_INF = __int_as_float(0xFF800000);
    const int t = threadIdx.x;
    const int lane = t & 31;
    const int wid  = t >> 5;

    const bool interior = (bx > 0) && (bx < WW/32 - 1) && (by > 0) && (by < HH/64 - 1);

    if (interior) {
        const float* base = Ri + (size_t)(r0 - 3) * WW + (c0 - 4);   // 16B aligned
        for (int idx = t; idx < 70*10; idx += 256) {
            int i = idx / 10, j4 = idx % 10;
            float4 v = *(const float4*)(base + (size_t)i * WW + j4*4);
            float4 o;
            o.x = (v.x > med) ? v.x : 0.f;
            o.y = (v.y > med) ? v.y : 0.f;
            o.z = (v.z > med) ? v.z : 0.f;
            o.w = (v.w > med) ? v.w : 0.f;
            *(float4*)&sxt[i*PTX + j4*4] = o;
        }
    } else {
        for (int idx = t; idx < 70*40; idx += 256) {
            int i = idx / 40, j = idx % 40;
            int gr = r0 + i - 3, gc = c0 + j - 4;
            float v = NEG_INF;
            if (gr >= 0 && gr < HH && gc >= 0 && gc < WW) {
                float R = Ri[(size_t)gr * WW + gc];
                v = (R > med) ? R : 0.f;
            }
            sxt[i*PTX + j] = v;
        }
    }
    __syncthreads();

    for (int tt = t; tt < 280; tt += 256) {
        int row = tt >> 2;
        int j0  = (tt & 3) << 3;
        float v[14];
        #pragma unroll
        for (int k = 0; k < 14; k++) v[k] = sxt[row*PTX + j0 + 1 + k];
        float suf[7], pre[7];
        suf[6] = v[6];
        #pragma unroll
        for (int i = 5; i >= 0; i--) suf[i] = fmaxf(v[i], suf[i+1]);
        pre[0] = v[7];
        #pragma unroll
        for (int i = 1; i < 7; i++) pre[i] = fmaxf(pre[i-1], v[7+i]);
        #pragma unroll
        for (int o = 0; o < 8; o++) {
            float m = (o == 0) ? suf[0] : ((o == 7) ? pre[6] : fmaxf(suf[o], pre[o-1]));
            shm[row*PTM + j0 + o] = m;
        }
    }
    __syncthreads();

    {
        const int col = lane;
        const int r0l = wid * 8;
        float v[14];
        #pragma unroll
        for (int k = 0; k < 14; k++) v[k] = shm[(r0l + k)*PTM + col];
        float suf[7], pre[7];
        suf[6] = v[6];
        #pragma unroll
        for (int i = 5; i >= 0; i--) suf[i] = fmaxf(v[i], suf[i+1]);
        pre[0] = v[7];
        #pragma unroll
        for (int i = 1; i < 7; i++) pre[i] = fmaxf(pre[i-1], v[7+i]);

        size_t obase = (size_t)n * HH * WW + (size_t)(r0 + r0l) * WW + (c0 + col);
        #pragma unroll
        for (int o = 0; o < 8; o++) {
            float m = (o == 0) ? suf[0] : ((o == 7) ? pre[6] : fmaxf(suf[o], pre[o-1]));
            float xt = sxt[(r0l + o + 3)*PTX + col + 4];
            out[obase + (size_t)o * WW] = (xt == m) ? xt : 0.f;
        }
    }
}

// ---------------- launch ----------------
extern "C" void kernel_launch(void* const* d_in, const int* in_sizes, int n_in,
                              void* d_out, int out_size) {
    const float* x     = (const float*)d_in[0];
    const float* gauss = (const float*)d_in[2];
    float* out = (float*)d_out;

    static int configured = 0;
    if (!configured) {
        cudaFuncSetAttribute(k_harris, cudaFuncAttributeMaxDynamicSharedMemorySize, SMEM_BYTES);
        cudaFuncSetAttribute(k_harris, cudaFuncAttributePreferredSharedMemoryCarveout, 100);
        configured = 1;
    }

    dim3 gh(WW/TC, HH/TR, NIMG);      // 64 x 64 x 4
    k_harris<<<gh, 256, SMEM_BYTES>>>(x, gauss);

    k_sel23<<<1024, 256>>>();

    dim3 gp(WW/32, HH/64, NIMG);
    k_pool<<<gp, 256>>>(out);
}

// round 17
// speedup vs baseline: 1.0467x; 1.0467x over previous
#include <cuda_runtime.h>
#include <math.h>

#define HH 2048
#define WW 2048
#define NIMG 4
#define TOT (NIMG*HH*WW)
#define RANK0 8388607u   // (TOT-1)/2

// harris tile geometry (32x32 output tile)
#define TR 32
#define TC 32
#define GR 40            // TR+8
#define SXR 42           // TR+10
#define SXW 48           // x tile cols (rel -8..39), float4-friendly
#define PX  52           // x pitch (multiple of 4 for STS.128)
#define PIX 41           // Ixy pitch (float2 units, odd)
#define PSH 33           // smoothed pitch (odd)
#define SIXY2 (GR*PIX)             // 1640 float2 = 3280 floats
#define SHCH (GR*PSH)              // 1320 floats per channel
#define SC_FLOATS (3*SHCH)         // 3960
#define SMEM_FLOATS (2*SIXY2 + SC_FLOATS)  // 7240
#define SMEM_BYTES (SMEM_FLOATS*4)         // 28960
#define HARRIS_BLOCKS ((WW/TC)*(HH/TR)*NIMG)  // 16384
#define SCAN_BLOCKS 1024

// ---------------- device scratch ----------------
__device__ float    g_R[TOT];
__device__ unsigned g_hist[2048];
__device__ unsigned g_hist21[1u<<21];   // 8MB second-level histogram (zeroed by harris)
__device__ unsigned g_part[SCAN_BLOCKS];
__device__ unsigned g_prefix, g_rank;
__device__ unsigned g_done1, g_done2, g_done3, g_phase;
__device__ float    g_med;

// ---------------- pass-1 select: warp-shuffle scan over 2048 bins ----------------
__device__ __forceinline__ void select_pass1() {
    __shared__ unsigned swsum[8];
    __shared__ unsigned sbase[8];
    const int t = threadIdx.x;
    const int lane = t & 31;
    const int wid  = t >> 5;
    const unsigned rank = RANK0;

    unsigned local[8];
    unsigned sum = 0;
    #pragma unroll
    for (int i = 0; i < 8; i++) {
        local[i] = *(volatile unsigned*)&g_hist[t*8 + i];
        sum += local[i];
    }
    unsigned run = sum;
    #pragma unroll
    for (int d = 1; d < 32; d <<= 1) {
        unsigned v = __shfl_up_sync(0xFFFFFFFFu, run, d);
        if (lane >= d) run += v;
    }
    if (lane == 31) swsum[wid] = run;
    __syncthreads();
    if (t < 8) {
        unsigned v = swsum[t];
        unsigned r = v;
        #pragma unroll
        for (int d = 1; d < 8; d <<= 1) {
            unsigned u = __shfl_up_sync(0xFFu, r, d, 8);
            if (t >= d) r += u;
        }
        sbase[t] = r - v;
    }
    __syncthreads();
    unsigned before = sbase[wid] + (run - sum);
    if (rank >= before && rank < before + sum) {
        unsigned cum = before;
        #pragma unroll
        for (int i = 0; i < 8; i++) {
            if (rank < cum + local[i]) {
                g_prefix = (unsigned)(t*8 + i) << 21;
                g_rank = rank - cum;
                break;
            }
            cum += local[i];
        }
    }
    __syncthreads();
    for (int i = t; i < 2048; i += 256) g_hist[i] = 0;
}

// ---------------- fused Sobel + products + separable gauss + R + hist1 ----------------
__global__ __launch_bounds__(256) void k_harris(const float* __restrict__ x,
                                                const float* __restrict__ g2) {
    extern __shared__ float smem[];
    float2* sIxy = (float2*)smem;          // GR x PIX float2 (Ix,Iy)
    float*  sC   = smem + 2*SIXY2;         // union: x tile (SXR*PX) then sh[3]
    unsigned* shist = (unsigned*)smem;     // aliases sIxy in phase 4

    __shared__ float s_w[9];
    __shared__ unsigned s_last;

    const int t = threadIdx.x;
    const int lane = t & 31;
    const int wid  = t >> 5;
    const int n   = blockIdx.z;
    const int r0g = blockIdx.y * TR;
    const int c0g = blockIdx.x * TC;
    const float* __restrict__ xi = x + (size_t)n * HH * WW;

    // zero g_hist21 slice (blocks 0..2047): 2048 * 256 * 16B = 8MB
    {
        unsigned fid = blockIdx.x + blockIdx.y * gridDim.x
                     + blockIdx.z * gridDim.x * gridDim.y;
        if (fid < 2048) {
            uint4 z = {0u,0u,0u,0u};
            ((uint4*)g_hist21)[fid * 256 + t] = z;
        }
    }

    if (t == 0) {
        double c = sqrt((double)g2[4*9 + 4]);
        for (int k = 0; k < 9; k++) s_w[k] = (float)((double)g2[4*9 + k] / c);
    }

    const bool interior = (blockIdx.x > 0) && (blockIdx.x < WW/TC - 1) &&
                          (blockIdx.y > 0) && (blockIdx.y < HH/TR - 1);

    // ---- phase 1: load x tile rows -5..36, cols -8..39 (float4 interior) ----
    if (interior) {
        const float* base = xi + (size_t)(r0g - 5) * WW + (c0g - 8);   // 16B aligned
        for (int idx = t; idx < SXR*12; idx += 256) {
            int i = idx / 12, j4 = idx % 12;
            float4 v = *(const float4*)(base + (size_t)i * WW + j4*4);
            *(float4*)&sC[i*PX + j4*4] = v;
        }
    } else {
        for (int idx = t; idx < SXR*SXW; idx += 256) {
            int i = idx / SXW, j = idx % SXW;
            int gr = r0g + i - 5, gc = c0g + j - 8;
            float v = 0.f;
            if (gr >= 0 && gr < HH && gc >= 0 && gc < WW) v = xi[(size_t)gr * WW + gc];
            sC[i*PX + j] = v;
        }
    }
    __syncthreads();

    float w[9];
    #pragma unroll
    for (int k = 0; k < 9; k++) w[k] = s_w[k];

    // ---- phase 2: sobel Ix,Iy at rel rows -4..35, rel cols -4..35 (packed stores) ----
    for (int task = t; task < GR*10; task += 256) {
        int i  = task / 10;
        int j0 = (task % 10) * 4;
        float a[3][6];
        #pragma unroll
        for (int r = 0; r < 3; r++)
            #pragma unroll
            for (int c = 0; c < 6; c++)
                a[r][c] = sC[(i + r)*PX + j0 + 3 + c];
        if (interior) {
            #pragma unroll
            for (int dj = 0; dj < 4; dj++) {
                float ix = (a[0][dj+2]-a[0][dj]) + 2.f*(a[1][dj+2]-a[1][dj]) + (a[2][dj+2]-a[2][dj]);
                float iy = (a[2][dj]-a[0][dj])   + 2.f*(a[2][dj+1]-a[0][dj+1]) + (a[2][dj+2]-a[0][dj+2]);
                sIxy[i*PIX + j0 + dj] = make_float2(ix, iy);
            }
        } else {
            int gr = r0g + i - 4;
            bool rok = (gr >= 0 && gr < HH);
            #pragma unroll
            for (int dj = 0; dj < 4; dj++) {
                int gc = c0g + j0 + dj - 4;
                float ix = 0.f, iy = 0.f;
                if (rok && gc >= 0 && gc < WW) {
                    ix = (a[0][dj+2]-a[0][dj]) + 2.f*(a[1][dj+2]-a[1][dj]) + (a[2][dj+2]-a[2][dj]);
                    iy = (a[2][dj]-a[0][dj])   + 2.f*(a[2][dj+1]-a[0][dj+1]) + (a[2][dj+2]-a[0][dj+2]);
                }
                sIxy[i*PIX + j0 + dj] = make_float2(ix, iy);
            }
        }
    }
    __syncthreads();

    // ---- phase 3: horizontal gauss of products (packed loads) ----
    for (int task = t; task < GR*8; task += 256) {
        int row = task >> 3;
        int j0  = (task & 7) << 2;
        const float2* bxy = &sIxy[row*PIX + j0];
        float ix[12], iy[12];
        #pragma unroll
        for (int p = 0; p < 12; p++) { float2 v = bxy[p]; ix[p] = v.x; iy[p] = v.y; }
        float s0[4] = {0,0,0,0}, s1[4] = {0,0,0,0}, s2[4] = {0,0,0,0};
        #pragma unroll
        for (int p = 0; p < 12; p++) {
            float pxx = ix[p]*ix[p];
            float pyy = iy[p]*iy[p];
            float pxy = ix[p]*iy[p];
            #pragma unroll
            for (int j = 0; j < 4; j++) {
                if (p - j >= 0 && p - j <= 8) {
                    float wk = w[p - j];
                    s0[j] += wk*pxx;
                    s1[j] += wk*pyy;
                    s2[j] += wk*pxy;
                }
            }
        }
        #pragma unroll
        for (int j = 0; j < 4; j++) {
            sC[0*SHCH + row*PSH + j0 + j] = s0[j];
            sC[1*SHCH + row*PSH + j0 + j] = s1[j];
            sC[2*SHCH + row*PSH + j0 + j] = s2[j];
        }
    }
    __syncthreads();

    for (int i = t; i < 2048; i += 256) shist[i] = 0;
    __syncthreads();

    // ---- phase 4: vertical gauss + R + histogram (4 rows/thread, scalar) ----
    {
        const int col = lane;
        const int r0l = wid * 4;
        float win[12], s0[4], s1[4];

        #pragma unroll
        for (int k = 0; k < 12; k++) win[k] = sC[0*SHCH + (r0l + k)*PSH + col];
        #pragma unroll
        for (int o = 0; o < 4; o++) {
            float s = 0.f;
            #pragma unroll
            for (int k = 0; k < 9; k++) s += w[k]*win[o + k];
            s0[o] = s;
        }
        #pragma unroll
        for (int k = 0; k < 12; k++) win[k] = sC[1*SHCH + (r0l + k)*PSH + col];
        #pragma unroll
        for (int o = 0; o < 4; o++) {
            float s = 0.f;
            #pragma unroll
            for (int k = 0; k < 9; k++) s += w[k]*win[o + k];
            s1[o] = s;
        }
        #pragma unroll
        for (int k = 0; k < 12; k++) win[k] = sC[2*SHCH + (r0l + k)*PSH + col];

        size_t obase = (size_t)n * HH * WW + (size_t)(r0g + r0l) * WW + (c0g + col);
        #pragma unroll
        for (int o = 0; o < 4; o++) {
            float s2 = 0.f;
            #pragma unroll
            for (int k = 0; k < 9; k++) s2 += w[k]*win[o + k];
            float det = s0[o]*s1[o] - s2*s2;
            float tr  = s0[o] + s1[o];
            float R   = det - 0.05f*tr*tr;
            g_R[obase + (size_t)o * WW] = R;

            unsigned b = __float_as_uint(R);
            unsigned u = b ^ ((b & 0x80000000u) ? 0xFFFFFFFFu : 0x80000000u);
            unsigned bin = u >> 21;
            unsigned peers = __match_any_sync(0xFFFFFFFFu, bin);
            if ((unsigned)(__ffs(peers) - 1) == (unsigned)lane)
                atomicAdd(&shist[bin], (unsigned)__popc(peers));
        }
    }
    __syncthreads();

    for (int i = t; i < 2048; i += 256) {
        unsigned c = shist[i];
        if (c) atomicAdd(&g_hist[i], c);
    }
    __threadfence();
    if (t == 0) s_last = (atomicAdd(&g_done1, 1) == HARRIS_BLOCKS - 1) ? 1u : 0u;
    __syncthreads();
    if (s_last) {
        __threadfence();
        select_pass1();
        if (t == 0) g_done1 = 0;
    }
}

// ---------------- single scan + 21-bit histogram + fused hierarchical select ----------------
__global__ __launch_bounds__(256) void k_scansel() {
    __shared__ unsigned s_last;
    __shared__ unsigned swsum[8], sbase[8];
    __shared__ unsigned s_chunk, s_rank;
    __shared__ unsigned sred[256];

    const int t = threadIdx.x;
    const unsigned lane = t & 31;
    const int wid = t >> 5;
    const float4* __restrict__ Rv = (const float4*)g_R;
    const size_t n4 = TOT / 4;
    const size_t stride = (size_t)gridDim.x * 256;

    // ---- phase A: scan R, match top-11 prefix, spread atomics into 2M bins ----
    const unsigned pfx_hi = g_prefix >> 21;
    for (size_t i4 = (size_t)blockIdx.x * 256 + t; i4 < n4; i4 += 2*stride) {
        float4 va = Rv[i4];
        float4 vb = Rv[i4 + stride];
        float vals[8] = {va.x, va.y, va.z, va.w, vb.x, vb.y, vb.z, vb.w};
        #pragma unroll
        for (int e = 0; e < 8; e++) {
            unsigned b = __float_as_uint(vals[e]);
            unsigned u = b ^ ((b & 0x80000000u) ? 0xFFFFFFFFu : 0x80000000u);
            bool match = ((u >> 21) == pfx_hi);
            unsigned bin = u & 0x1FFFFFu;
            unsigned bal = __ballot_sync(0xFFFFFFFFu, match);
            if (match) {
                unsigned peers = __match_any_sync(bal, bin);
                if ((unsigned)(__ffs(peers) - 1) == lane)
                    atomicAdd(&g_hist21[bin], (unsigned)__popc(peers));
            }
        }
    }
    __threadfence();
    if (t == 0) s_last = (atomicAdd(&g_done2, 1) == gridDim.x - 1) ? 1u : 0u;
    __syncthreads();
    if (s_last) {
        __threadfence();
        if (t == 0) atomicExch(&g_phase, 1u);
    } else {
        if (t == 0) { while (*(volatile unsigned*)&g_phase == 0u) __nanosleep(64); }
        __syncthreads();
    }

    // ---- phase B: block b sums its 2048-bin chunk ----
    {
        unsigned sum = 0;
        const unsigned* hb = g_hist21 + (size_t)blockIdx.x * 2048;
        #pragma unroll
        for (int i = 0; i < 8; i++) sum += __ldcg(&hb[t + i*256]);
        sred[t] = sum;
        __syncthreads();
        for (int d = 128; d > 0; d >>= 1) {
            if (t < d) sred[t] += sred[t + d];
            __syncthreads();
        }
        if (t == 0) g_part[blockIdx.x] = sred[0];
    }
    __threadfence();
    if (t == 0) s_last = (atomicAdd(&g_done3, 1) == gridDim.x - 1) ? 1u : 0u;
    __syncthreads();
    if (!s_last) return;
    __threadfence();

    // ---- phase C: hierarchical select (last-done block only) ----
    const unsigned rank = *(volatile unsigned*)&g_rank;

    // level 1: over 1024 chunk sums (4/thread)
    {
        unsigned l1[4];
        unsigned sum = 0;
        #pragma unroll
        for (int i = 0; i < 4; i++) { l1[i] = __ldcg(&g_part[t*4 + i]); sum += l1[i]; }
        unsigned run = sum;
        #pragma unroll
        for (int d = 1; d < 32; d <<= 1) {
            unsigned v = __shfl_up_sync(0xFFFFFFFFu, run, d);
            if ((int)lane >= d) run += v;
        }
        if (lane == 31) swsum[wid] = run;
        __syncthreads();
        if (t < 8) {
            unsigned v = swsum[t];
            unsigned r = v;
            #pragma unroll
            for (int d = 1; d < 8; d <<= 1) {
                unsigned u = __shfl_up_sync(0xFFu, r, d, 8);
                if (t >= d) r += u;
            }
            sbase[t] = r - v;
        }
        __syncthreads();
        unsigned before = sbase[wid] + (run - sum);
        if (rank >= before && rank < before + sum) {
            unsigned cum = before;
            #pragma unroll
            for (int i = 0; i < 4; i++) {
                if (rank < cum + l1[i]) { s_chunk = (unsigned)(t*4 + i); s_rank = rank - cum; break; }
                cum += l1[i];
            }
        }
        __syncthreads();
    }

    // level 2: within chunk (2048 bins, 8/thread)
    {
        const unsigned base = s_chunk * 2048;
        const unsigned r2 = s_rank;
        unsigned l2[8];
        unsigned sum = 0;
        #pragma unroll
        for (int i = 0; i < 8; i++) { l2[i] = __ldcg(&g_hist21[base + t*8 + i]); sum += l2[i]; }
        unsigned run = sum;
        #pragma unroll
        for (int d = 1; d < 32; d <<= 1) {
            unsigned v = __shfl_up_sync(0xFFFFFFFFu, run, d);
            if ((int)lane >= d) run += v;
        }
        if (lane == 31) swsum[wid] = run;
        __syncthreads();
        if (t < 8) {
            unsigned v = swsum[t];
            unsigned r = v;
            #pragma unroll
            for (int d = 1; d < 8; d <<= 1) {
                unsigned u = __shfl_up_sync(0xFFu, r, d, 8);
                if (t >= d) r += u;
            }
            sbase[t] = r - v;
        }
        __syncthreads();
        unsigned before = sbase[wid] + (run - sum);
        if (r2 >= before && r2 < before + sum) {
            unsigned cum = before;
            #pragma unroll
            for (int i = 0; i < 8; i++) {
                if (r2 < cum + l2[i]) {
                    unsigned np = g_prefix | (base + (unsigned)(t*8 + i));
                    unsigned bb = (np & 0x80000000u) ? (np ^ 0x80000000u) : ~np;
                    g_med = __uint_as_float(bb);
                    break;
                }
                cum += l2[i];
            }
        }
        __syncthreads();
    }
    if (t == 0) { g_done2 = 0; g_done3 = 0; g_phase = 0; }
}

// ---------------- threshold + 7x7 NMS (float4 loads, prefix/suffix max both axes) ----------------
#define PTX 44   // sxt pitch (multiple of 4 for STS.128)
#define PTM 33   // hmax pitch (odd)
__global__ __launch_bounds__(256) void k_pool(float* __restrict__ out) {
    __shared__ float sxt[70*PTX];
    __shared__ float shm[70*PTM];
    const int bx = blockIdx.x, by = blockIdx.y, n = blockIdx.z;
    const int r0 = by * 64, c0 = bx * 32;
    const float* __restrict__ Ri = g_R + (size_t)n * HH * WW;
    const float med = g_med;
    const float NEG_INF = __int_as_float(0xFF800000);
    const int t = threadIdx.x;
    const int lane = t & 31;
    const int wid  = t >> 5;

    const bool interior = (bx > 0) && (bx < WW/32 - 1) && (by > 0) && (by < HH/64 - 1);

    if (interior) {
        const float* base = Ri + (size_t)(r0 - 3) * WW + (c0 - 4);   // 16B aligned
        for (int idx = t; idx < 70*10; idx += 256) {
            int i = idx / 10, j4 = idx % 10;
            float4 v = *(const float4*)(base + (size_t)i * WW + j4*4);
            float4 o;
            o.x = (v.x > med) ? v.x : 0.f;
            o.y = (v.y > med) ? v.y : 0.f;
            o.z = (v.z > med) ? v.z : 0.f;
            o.w = (v.w > med) ? v.w : 0.f;
            *(float4*)&sxt[i*PTX + j4*4] = o;
        }
    } else {
        for (int idx = t; idx < 70*40; idx += 256) {
            int i = idx / 40, j = idx % 40;
            int gr = r0 + i - 3, gc = c0 + j - 4;
            float v = NEG_INF;
            if (gr >= 0 && gr < HH && gc >= 0 && gc < WW) {
                float R = Ri[(size_t)gr * WW + gc];
                v = (R > med) ? R : 0.f;
            }
            sxt[i*PTX + j] = v;
        }
    }
    __syncthreads();

    for (int tt = t; tt < 280; tt += 256) {
        int row = tt >> 2;
        int j0  = (tt & 3) << 3;
        float v[14];
        #pragma unroll
        for (int k = 0; k < 14; k++) v[k] = sxt[row*PTX + j0 + 1 + k];
        float suf[7], pre[7];
        suf[6] = v[6];
        #pragma unroll
        for (int i = 5; i >= 0; i--) suf[i] = fmaxf(v[i], suf[i+1]);
        pre[0] = v[7];
        #pragma unroll
        for (int i = 1; i < 7; i++) pre[i] = fmaxf(pre[i-1], v[7+i]);
        #pragma unroll
        for (int o = 0; o < 8; o++) {
            float m = (o == 0) ? suf[0] : ((o == 7) ? pre[6] : fmaxf(suf[o], pre[o-1]));
            shm[row*PTM + j0 + o] = m;
        }
    }
    __syncthreads();

    {
        const int col = lane;
        const int r0l = wid * 8;
        float v[14];
        #pragma unroll
        for (int k = 0; k < 14; k++) v[k] = shm[(r0l + k)*PTM + col];
        float suf[7], pre[7];
        suf[6] = v[6];
        #pragma unroll
        for (int i = 5; i >= 0; i--) suf[i] = fmaxf(v[i], suf[i+1]);
        pre[0] = v[7];
        #pragma unroll
        for (int i = 1; i < 7; i++) pre[i] = fmaxf(pre[i-1], v[7+i]);

        size_t obase = (size_t)n * HH * WW + (size_t)(r0 + r0l) * WW + (c0 + col);
        #pragma unroll
        for (int o = 0; o < 8; o++) {
            float m = (o == 0) ? suf[0] : ((o == 7) ? pre[6] : fmaxf(suf[o], pre[o-1]));
            float xt = sxt[(r0l + o + 3)*PTX + col + 4];
            out[obase + (size_t)o * WW] = (xt == m) ? xt : 0.f;
        }
    }
}

// ---------------- launch ----------------
extern "C" void kernel_launch(void* const* d_in, const int* in_sizes, int n_in,
                              void* d_out, int out_size) {
    const float* x     = (const float*)d_in[0];
    const float* gauss = (const float*)d_in[2];
    float* out = (float*)d_out;

    static int configured = 0;
    if (!configured) {
        cudaFuncSetAttribute(k_harris, cudaFuncAttributeMaxDynamicSharedMemorySize, SMEM_BYTES);
        cudaFuncSetAttribute(k_harris, cudaFuncAttributePreferredSharedMemoryCarveout, 100);
        configured = 1;
    }

    dim3 gh(WW/TC, HH/TR, NIMG);      // 64 x 64 x 4
    k_harris<<<gh, 256, SMEM_BYTES>>>(x, gauss);

    k_scansel<<<SCAN_BLOCKS, 256>>>();

    dim3 gp(WW/32, HH/64, NIMG);
    k_pool<<<gp, 256>>>(out);
}